// round 2
// baseline (speedup 1.0000x reference)
#include <cuda_runtime.h>

// BinsCombinerLayer: out[b] = (1/NUM_BINS) * sum_{n,s} inputs[b,n,s] * centroids[n,s]
// B=32768, NUM_BINS=16, BIN_SIZE=128. Pure HBM-bound streaming reduction
// (268 MB read once, 0.5 FLOP/byte). Persistent-grid version: each warp
// grid-strides over examples so loads for example i+1 overlap the
// shuffle-reduce of example i, and centroid staging is amortized.

#define B_TOTAL       32768
#define ROW_FLOATS    2048               // NUM_BINS * BIN_SIZE
#define ROW_VEC4      (ROW_FLOATS / 4)   // 512 float4 per row
#define VEC_PER_LANE  (ROW_VEC4 / 32)    // 16 float4 per lane per example
#define THREADS       256
#define WARPS_PER_BLOCK (THREADS / 32)
#define GRID_BLOCKS   592                // 4 blocks per SM on 148 SMs
#define INV_NUM_BINS  (1.0f / 16.0f)

__global__ __launch_bounds__(THREADS)
void bins_combiner_kernel(const float* __restrict__ inputs,
                          const float* __restrict__ centroids,
                          float* __restrict__ out)
{
    __shared__ float4 sc[ROW_VEC4];   // 8 KB centroid table, block-resident

    // Cooperative centroid stage (coalesced float4), once per persistent block
    const float4* c4 = reinterpret_cast<const float4*>(centroids);
    for (int i = threadIdx.x; i < ROW_VEC4; i += THREADS) {
        sc[i] = c4[i];
    }
    __syncthreads();

    const int warp  = threadIdx.x >> 5;
    const int lane  = threadIdx.x & 31;
    const int gwarp = blockIdx.x * WARPS_PER_BLOCK + warp;
    const int nwarps = GRID_BLOCKS * WARPS_PER_BLOCK;   // 4736 warps

    // Preload this lane's centroid slice into registers once (reused ~7x).
    float4 creg[VEC_PER_LANE];
    #pragma unroll
    for (int k = 0; k < VEC_PER_LANE; ++k) {
        creg[k] = sc[lane + 32 * k];
    }

    // Grid-stride over examples: ~6.92 examples per warp.
    for (int b = gwarp; b < B_TOTAL; b += nwarps) {
        const float4* __restrict__ row =
            reinterpret_cast<const float4*>(inputs + (size_t)b * ROW_FLOATS);

        float acc = 0.0f;
        #pragma unroll
        for (int k = 0; k < VEC_PER_LANE; ++k) {
            // evict-first streaming load: zero reuse, keep L2 for centroids
            float4 v = __ldcs(&row[lane + 32 * k]);
            acc += v.x * creg[k].x;
            acc += v.y * creg[k].y;
            acc += v.z * creg[k].z;
            acc += v.w * creg[k].w;
        }

        // Warp butterfly reduce
        #pragma unroll
        for (int off = 16; off > 0; off >>= 1) {
            acc += __shfl_xor_sync(0xFFFFFFFFu, acc, off);
        }

        if (lane == 0) {
            out[b] = acc * INV_NUM_BINS;
        }
    }
}

extern "C" void kernel_launch(void* const* d_in, const int* in_sizes, int n_in,
                              void* d_out, int out_size)
{
    const float* inputs    = (const float*)d_in[0];   // [32768, 16, 128] f32
    const float* centroids = (const float*)d_in[1];   // [16, 128] f32
    float* out             = (float*)d_out;           // [32768] f32

    bins_combiner_kernel<<<GRID_BLOCKS, THREADS>>>(inputs, centroids, out);
}

// round 3
// speedup vs baseline: 1.0066x; 1.0066x over previous
#include <cuda_runtime.h>

// BinsCombinerLayer: out[b] = (1/NUM_BINS) * sum_{n,s} inputs[b,n,s] * centroids[n,s]
// B=32768, NUM_BINS=16, BIN_SIZE=128. Pure HBM-bound streaming reduction
// (268 MB read once). Persistent grid (no wave-quantization tail) +
// smem-resident centroids (no register blowup: R2's creg cache cost 64 regs
// and dropped occupancy to 24%).

#define B_TOTAL       32768
#define ROW_FLOATS    2048               // NUM_BINS * BIN_SIZE
#define ROW_VEC4      (ROW_FLOATS / 4)   // 512 float4 per row
#define VEC_PER_LANE  (ROW_VEC4 / 32)    // 16 float4 per lane per example
#define THREADS       256
#define WARPS_PER_BLOCK (THREADS / 32)
#define BLOCKS_PER_SM 8
#define GRID_BLOCKS   (148 * BLOCKS_PER_SM)   // 1184 persistent blocks
#define INV_NUM_BINS  (1.0f / 16.0f)

__global__ __launch_bounds__(THREADS, BLOCKS_PER_SM)
void bins_combiner_kernel(const float* __restrict__ inputs,
                          const float* __restrict__ centroids,
                          float* __restrict__ out)
{
    __shared__ float4 sc[ROW_VEC4];   // 8 KB centroid table, block-resident

    // Cooperative centroid stage (coalesced float4), once per persistent block
    const float4* c4 = reinterpret_cast<const float4*>(centroids);
    for (int i = threadIdx.x; i < ROW_VEC4; i += THREADS) {
        sc[i] = c4[i];
    }
    __syncthreads();

    const int warp   = threadIdx.x >> 5;
    const int lane   = threadIdx.x & 31;
    const int gwarp  = blockIdx.x * WARPS_PER_BLOCK + warp;
    const int nwarps = GRID_BLOCKS * WARPS_PER_BLOCK;   // 9472 warps

    // Grid-stride over examples (~3.46 examples per warp): loads of the next
    // example overlap the shuffle-reduce of the previous one.
    for (int b = gwarp; b < B_TOTAL; b += nwarps) {
        const float4* __restrict__ row =
            reinterpret_cast<const float4*>(inputs + (size_t)b * ROW_FLOATS);

        float acc = 0.0f;
        #pragma unroll
        for (int k = 0; k < VEC_PER_LANE; ++k) {
            const int idx = lane + 32 * k;
            float4 v = __ldcs(&row[idx]);   // evict-first: stream-once data
            float4 c = sc[idx];             // smem read, conflict-free
            acc += v.x * c.x;
            acc += v.y * c.y;
            acc += v.z * c.z;
            acc += v.w * c.w;
        }

        // Warp butterfly reduce
        #pragma unroll
        for (int off = 16; off > 0; off >>= 1) {
            acc += __shfl_xor_sync(0xFFFFFFFFu, acc, off);
        }

        if (lane == 0) {
            out[b] = acc * INV_NUM_BINS;
        }
    }
}

extern "C" void kernel_launch(void* const* d_in, const int* in_sizes, int n_in,
                              void* d_out, int out_size)
{
    const float* inputs    = (const float*)d_in[0];   // [32768, 16, 128] f32
    const float* centroids = (const float*)d_in[1];   // [16, 128] f32
    float* out             = (float*)d_out;           // [32768] f32

    bins_combiner_kernel<<<GRID_BLOCKS, THREADS>>>(inputs, centroids, out);
}